// round 17
// baseline (speedup 1.0000x reference)
#include <cuda_runtime.h>
#include <cuda_fp16.h>
#include <math.h>
#include <stdint.h>

// Problem constants
#define Bz     2
#define SEQ    2048
#define EMB    1024
#define NHEAD  16
#define HDIM   64
#define HIDDEN 4096
#define TOK    (Bz * SEQ)          // 4096 rows
#define BH     (Bz * NHEAD)        // 32 batched heads

typedef __half fp16;

// ===================== MMA / async primitives (non-'a' PTX) ============
__device__ __forceinline__ void ldm_x4(uint32_t* r, uint32_t addr) {
    asm volatile("ldmatrix.sync.aligned.m8n8.x4.shared.b16 {%0,%1,%2,%3}, [%4];"
        : "=r"(r[0]), "=r"(r[1]), "=r"(r[2]), "=r"(r[3]) : "r"(addr));
}
__device__ __forceinline__ void mma_fp16(float* c, const uint32_t* a,
                                         uint32_t b0, uint32_t b1) {
    asm volatile(
        "mma.sync.aligned.m16n8k16.row.col.f32.f16.f16.f32 "
        "{%0,%1,%2,%3}, {%4,%5,%6,%7}, {%8,%9}, {%0,%1,%2,%3};"
        : "+f"(c[0]), "+f"(c[1]), "+f"(c[2]), "+f"(c[3])
        : "r"(a[0]), "r"(a[1]), "r"(a[2]), "r"(a[3]), "r"(b0), "r"(b1));
}
__device__ __forceinline__ uint32_t smem_to_u32(const void* p) {
    uint32_t a;
    asm("{ .reg .u64 t; cvta.to.shared.u64 t, %1; cvt.u32.u64 %0, t; }" : "=r"(a) : "l"(p));
    return a;
}
#define SW128(off) ((off) ^ (((off) >> 3) & 0x70))

#define CP_ASYNC16(saddr, gptr) \
    asm volatile("cp.async.cg.shared.global [%0], [%1], 16;" \
        :: "r"((uint32_t)(saddr)), "l"(gptr))
#define CP_COMMIT() asm volatile("cp.async.commit_group;" ::: "memory")
#define CP_WAIT2()  asm volatile("cp.async.wait_group 2;" ::: "memory")
#define CP_WAIT1()  asm volatile("cp.async.wait_group 1;" ::: "memory")
#define CP_WAIT0()  asm volatile("cp.async.wait_group 0;" ::: "memory")

__device__ __forceinline__ uint32_t pack_fp16(float a, float b) {
    __half2 h;
    h.x = __float2half(a);
    h.y = __float2half(b);
    return *(uint32_t*)&h;
}

// ===================== scratch =========================================
__device__ fp16  g_wqkvT[3 * EMB * EMB];
__device__ fp16  g_wprojT[EMB * EMB];
__device__ fp16  g_wfc1T[HIDDEN * EMB];
__device__ fp16  g_wfc2T[EMB * HIDDEN];
__device__ fp16  g_ln1[TOK * EMB];
__device__ fp16  g_q[BH * SEQ * HDIM];                 // scaled, single
__device__ fp16  g_k[BH * SEQ * HDIM];                 // single
__device__ float g_v[TOK * EMB];                       // (b,n,h*64+d) fp32
__device__ fp16  g_vt[BH * HDIM * SEQ];                // single
__device__ fp16  g_am[TOK * EMB];
__device__ float g_x1[TOK * EMB];
__device__ fp16  g_ln2[TOK * EMB];
__device__ fp16  g_h[TOK * HIDDEN];

__device__ __forceinline__ float gelu_exact(float x) {
    return 0.5f * x * (1.0f + erff(x * 0.70710678118654752440f));
}

// ===================== fp16 1-pass GEMM (3-stage cp.async) =============
// D[M,N] = alpha*(A @ B^T). A[M,K], B[N,K] single fp16.
#define EPI_ALPHA    0
#define EPI_BIAS     1
#define EPI_BIAS_RES 2
#define EPI_H        3
#define EPI_GELU_H   4
#define EPI_QKV      5   // fused q/k/v extraction (bias included)

template<int BN, int WM, int WN, int EPI>
__global__ __launch_bounds__(256, 1)
void gemm_mma(const fp16* __restrict__ A, const fp16* __restrict__ B,
              const float* __restrict__ bias, const float* __restrict__ resid,
              float* __restrict__ C, fp16* __restrict__ Ch,
              fp16* __restrict__ Qo, fp16* __restrict__ Ko,
              float* __restrict__ Vo,
              int M, int N, int K, int ldc,
              long long sA, long long sB,
              int hdiv, long long sCb, long long sCh,
              float alpha)
{
    constexpr int BK = 64;
    constexpr int OFF_B = 128 * 128;             // A tile = 16 KB
    constexpr int BUFB  = OFF_B + BN * 128;      // bytes per buffer
    constexpr int WGC = BN / WN;
    constexpr int MT  = WM / 16;
    constexpr int NT  = WN / 8;
    constexpr int NG  = WN / 16;

    extern __shared__ char sm[];
    const uint32_t smb = smem_to_u32(sm);
    const int tid = threadIdx.x, wid = tid >> 5, lane = tid & 31;
    const int bm = blockIdx.y * 128, bn = blockIdx.x * BN, z = blockIdx.z;
    const int wm0 = (wid / WGC) * WM, wn0 = (wid % WGC) * WN;

    A += (long long)z * sA;
    B += (long long)z * sB;
    const long long coff = (long long)(z / hdiv) * sCb + (long long)(z % hdiv) * sCh;

    float acc[MT][NT][4];
#pragma unroll
    for (int i = 0; i < MT; i++)
#pragma unroll
        for (int j = 0; j < NT; j++)
#pragma unroll
            for (int t = 0; t < 4; t++) acc[i][j][t] = 0.0f;

    const int swz   = lane & 7;
    const int aHalf = lane >> 4;
    const int bHalf = (lane >> 3) & 1;
    int aRowOff[MT], bRowOff[NG];
#pragma unroll
    for (int mt = 0; mt < MT; mt++)
        aRowOff[mt] = (wm0 + mt * 16 + (lane & 15)) * 128;
#pragma unroll
    for (int ng = 0; ng < NG; ng++)
        bRowOff[ng] = (wn0 + ng * 16 + (lane & 7) + ((lane >> 4) << 3)) * 128;

    auto stage = [&](int c, uint32_t base) {
        const long long k0 = (long long)c * BK;
        const fp16* a0 = A + (long long)bm * K + k0;
#pragma unroll
        for (int i = tid; i < 128 * 8; i += 256) {
            int r = i >> 3, u = i & 7;
            int sw = SW128(r * 128 + u * 16);
            CP_ASYNC16(smb + base + sw, a0 + (long long)r * K + u * 8);
        }
        const fp16* b0 = B + (long long)bn * K + k0;
#pragma unroll
        for (int i = tid; i < BN * 8; i += 256) {
            int r = i >> 3, u = i & 7;
            int sw = SW128(r * 128 + u * 16);
            CP_ASYNC16(smb + base + OFF_B + sw, b0 + (long long)r * K + u * 8);
        }
        CP_COMMIT();
    };

    const int nch = K / BK;
    stage(0, 0);
    if (nch > 1) stage(1, BUFB);
    for (int c = 0; c < nch; c++) {
        const uint32_t cur = (uint32_t)(c % 3) * BUFB;
        if (c + 2 < nch) {
            stage(c + 2, (uint32_t)((c + 2) % 3) * BUFB);
            CP_WAIT2();
        } else if (c + 1 < nch) {
            CP_WAIT1();
        } else {
            CP_WAIT0();
        }
        __syncthreads();

#pragma unroll
        for (int ks = 0; ks < BK / 16; ks++) {
            const uint32_t ca = (uint32_t)(((2 * ks + aHalf) ^ swz) * 16);
            const uint32_t cb = (uint32_t)(((2 * ks + bHalf) ^ swz) * 16);
            uint32_t ah[MT][4], br[NG][4];
#pragma unroll
            for (int mt = 0; mt < MT; mt++)
                ldm_x4(ah[mt], smb + cur + aRowOff[mt] + ca);
#pragma unroll
            for (int ng = 0; ng < NG; ng++)
                ldm_x4(br[ng], smb + cur + OFF_B + bRowOff[ng] + cb);
#pragma unroll
            for (int mt = 0; mt < MT; mt++)
#pragma unroll
                for (int nt = 0; nt < NT; nt++)
                    mma_fp16(acc[mt][nt], ah[mt],
                             br[nt >> 1][(nt & 1) * 2], br[nt >> 1][(nt & 1) * 2 + 1]);
        }
        __syncthreads();
    }

#pragma unroll
    for (int mt = 0; mt < MT; mt++) {
#pragma unroll
        for (int half = 0; half < 2; half++) {
            const long long row = bm + wm0 + mt * 16 + (lane >> 2) + half * 8;
#pragma unroll
            for (int nt = 0; nt < NT; nt++) {
                const int col = bn + wn0 + nt * 8 + (lane & 3) * 2;
                float v0 = acc[mt][nt][half * 2 + 0] * alpha;
                float v1 = acc[mt][nt][half * 2 + 1] * alpha;
                if (EPI == EPI_BIAS || EPI == EPI_BIAS_RES || EPI == EPI_GELU_H || EPI == EPI_QKV) {
                    v0 += bias[col]; v1 += bias[col + 1];
                }
                if (EPI == EPI_BIAS_RES) {
                    const float* rp = resid + coff + row * (long long)ldc + col;
                    v0 += rp[0]; v1 += rp[1];
                }
                if (EPI == EPI_GELU_H) {
                    v0 = gelu_exact(v0); v1 = gelu_exact(v1);
                }
                if (EPI == EPI_QKV) {
                    const int region = col >> 10;       // 0=Q 1=K 2=V (warp-uniform)
                    const int cc = col & 1023;
                    const int h = cc >> 6, d = cc & 63;
                    const long long b = row >> 11, n = row & 2047;
                    if (region == 2) {
                        float2 w; w.x = v0; w.y = v1;
                        *(float2*)(Vo + row * EMB + cc) = w;
                    } else {
                        const long long dst = ((b * NHEAD + h) * SEQ + n) * HDIM + d;
                        if (region == 0) {
                            __half2 x; x.x = __float2half(v0 * 0.125f);
                            x.y = __float2half(v1 * 0.125f);
                            *(__half2*)(Qo + dst) = x;
                        } else {
                            __half2 x; x.x = __float2half(v0);
                            x.y = __float2half(v1);
                            *(__half2*)(Ko + dst) = x;
                        }
                    }
                } else {
                    const long long o = coff + row * (long long)ldc + col;
                    if (EPI == EPI_ALPHA || EPI == EPI_BIAS || EPI == EPI_BIAS_RES) {
                        float2 w; w.x = v0; w.y = v1;
                        *(float2*)(C + o) = w;
                    } else {
                        __half2 hh; hh.x = __float2half(v0); hh.y = __float2half(v1);
                        *(__half2*)(Ch + o) = hh;
                    }
                }
            }
        }
    }
}

// ===================== Flash attention v4 (single-pass fp16) ===========
// Grid (SEQ/128, BH), 256 threads, 2 CTAs/SM. Q tile 128, KV tile 64
// double-buffered. S = Qf*Kf; O += Pf*Vf. smem 48 KB.
__global__ __launch_bounds__(256, 2)
void flash_kernel(const fp16* __restrict__ Qf, const fp16* __restrict__ Kf,
                  const fp16* __restrict__ Vf, fp16* __restrict__ O)
{
    constexpr int OFF_K = 16384;
    constexpr int OFF_V = 32768;
    constexpr int KBUF  = 8192;
    extern __shared__ char sm[];
    const uint32_t smb = smem_to_u32(sm);
    const int tid = threadIdx.x, wid = tid >> 5, lane = tid & 31;
    const int bh = blockIdx.y, q0 = blockIdx.x * 128;
    const long long qkbase = (long long)bh * SEQ * HDIM;
    const long long vbase  = (long long)bh * HDIM * SEQ;
    const int swz = lane & 7;

#pragma unroll
    for (int i = tid; i < 128 * 8; i += 256) {
        int r = i >> 3, u = i & 7;
        int sw = SW128(r * 128 + u * 16);
        CP_ASYNC16(smb + sw, Qf + qkbase + (long long)(q0 + r) * HDIM + u * 8);
    }
    CP_COMMIT();

    auto stage = [&](int t, int buf) {
        const int kv0 = t * 64;
        const uint32_t kb = OFF_K + buf * KBUF, vb = OFF_V + buf * KBUF;
#pragma unroll
        for (int i = tid; i < 64 * 8; i += 256) {
            int r = i >> 3, u = i & 7;
            int sw = SW128(r * 128 + u * 16);
            CP_ASYNC16(smb + kb + sw, Kf + qkbase + (long long)(kv0 + r) * HDIM + u * 8);
            CP_ASYNC16(smb + vb + sw, Vf + vbase + (long long)r * SEQ + kv0 + u * 8);
        }
        CP_COMMIT();
    };
    stage(0, 0);
    CP_WAIT0();
    __syncthreads();

    uint32_t qf[4][4];
    {
        const int aRowOff = (wid * 16 + (lane & 15)) * 128;
        const int aHalf = lane >> 4;
#pragma unroll
        for (int ks = 0; ks < 4; ks++) {
            const uint32_t ca = (uint32_t)(((2 * ks + aHalf) ^ swz) * 16);
            ldm_x4(qf[ks], smb + aRowOff + ca);
        }
    }

    float Oacc[8][4];
#pragma unroll
    for (int i = 0; i < 8; i++)
#pragma unroll
        for (int t = 0; t < 4; t++) Oacc[i][t] = 0.0f;
    float mrow[2] = {-1e30f, -1e30f};
    float lrow[2] = {0.0f, 0.0f};

    const int kRowOff = (lane & 7) + ((lane >> 4) << 3);
    const int bHalf = (lane >> 3) & 1;

    for (int t = 0; t < SEQ / 64; t++) {
        const int buf = t & 1;
        if (t + 1 < SEQ / 64) { stage(t + 1, buf ^ 1); CP_WAIT1(); }
        else                  { CP_WAIT0(); }
        __syncthreads();
        const uint32_t kb = OFF_K + buf * KBUF, vb = OFF_V + buf * KBUF;

        // ---- S = Qf Kf^T ----
        float S[8][4];
#pragma unroll
        for (int j = 0; j < 8; j++)
#pragma unroll
            for (int c = 0; c < 4; c++) S[j][c] = 0.0f;
#pragma unroll
        for (int g = 0; g < 4; g++) {
            const int bRow = (g * 16 + kRowOff) * 128;
#pragma unroll
            for (int ks = 0; ks < 4; ks++) {
                const uint32_t cb = (uint32_t)(((2 * ks + bHalf) ^ swz) * 16);
                uint32_t k4[4];
                ldm_x4(k4, smb + kb + bRow + cb);
                mma_fp16(S[2 * g],     qf[ks], k4[0], k4[1]);
                mma_fp16(S[2 * g + 1], qf[ks], k4[2], k4[3]);
            }
        }

        // ---- online softmax ----
        float mt0 = -1e30f, mt1 = -1e30f;
#pragma unroll
        for (int j = 0; j < 8; j++) {
            mt0 = fmaxf(mt0, fmaxf(S[j][0], S[j][1]));
            mt1 = fmaxf(mt1, fmaxf(S[j][2], S[j][3]));
        }
        mt0 = fmaxf(mt0, __shfl_xor_sync(0xffffffffu, mt0, 1));
        mt0 = fmaxf(mt0, __shfl_xor_sync(0xffffffffu, mt0, 2));
        mt1 = fmaxf(mt1, __shfl_xor_sync(0xffffffffu, mt1, 1));
        mt1 = fmaxf(mt1, __shfl_xor_sync(0xffffffffu, mt1, 2));
        const float mn0 = fmaxf(mrow[0], mt0), mn1 = fmaxf(mrow[1], mt1);
        const float sc0 = __expf(mrow[0] - mn0), sc1 = __expf(mrow[1] - mn1);
        float rs0 = 0.0f, rs1 = 0.0f;
#pragma unroll
        for (int j = 0; j < 8; j++) {
            S[j][0] = __expf(S[j][0] - mn0);
            S[j][1] = __expf(S[j][1] - mn0);
            S[j][2] = __expf(S[j][2] - mn1);
            S[j][3] = __expf(S[j][3] - mn1);
            rs0 += S[j][0] + S[j][1];
            rs1 += S[j][2] + S[j][3];
        }
        rs0 += __shfl_xor_sync(0xffffffffu, rs0, 1);
        rs0 += __shfl_xor_sync(0xffffffffu, rs0, 2);
        rs1 += __shfl_xor_sync(0xffffffffu, rs1, 1);
        rs1 += __shfl_xor_sync(0xffffffffu, rs1, 2);
        lrow[0] = lrow[0] * sc0 + rs0;
        lrow[1] = lrow[1] * sc1 + rs1;
        mrow[0] = mn0; mrow[1] = mn1;
#pragma unroll
        for (int i = 0; i < 8; i++) {
            Oacc[i][0] *= sc0; Oacc[i][1] *= sc0;
            Oacc[i][2] *= sc1; Oacc[i][3] *= sc1;
        }

        // ---- O += P Vf ----
#pragma unroll
        for (int j = 0; j < 4; j++) {
            uint32_t ah[4];
            ah[0] = pack_fp16(S[2*j][0],   S[2*j][1]);
            ah[1] = pack_fp16(S[2*j][2],   S[2*j][3]);
            ah[2] = pack_fp16(S[2*j+1][0], S[2*j+1][1]);
            ah[3] = pack_fp16(S[2*j+1][2], S[2*j+1][3]);

            const uint32_t cv = (uint32_t)(((2 * j + bHalf) ^ swz) * 16);
#pragma unroll
            for (int vg = 0; vg < 4; vg++) {
                const int vRow = (vg * 16 + kRowOff) * 128;
                uint32_t v4[4];
                ldm_x4(v4, smb + vb + vRow + cv);
                mma_fp16(Oacc[2 * vg],     ah, v4[0], v4[1]);
                mma_fp16(Oacc[2 * vg + 1], ah, v4[2], v4[3]);
            }
        }
        __syncthreads();
    }

    // epilogue: merged-head single fp16
    const float inv0 = 1.0f / lrow[0], inv1 = 1.0f / lrow[1];
    const int b = bh / NHEAD, hh = bh % NHEAD;
    const long long tok0 = (long long)b * SEQ + q0 + wid * 16 + (lane >> 2);
    const int col0 = hh * HDIM + (lane & 3) * 2;
#pragma unroll
    for (int vt = 0; vt < 8; vt++) {
        float v0 = Oacc[vt][0] * inv0, v1 = Oacc[vt][1] * inv0;
        float v2 = Oacc[vt][2] * inv1, v3 = Oacc[vt][3] * inv1;
        long long o = tok0 * EMB + col0 + vt * 8;
        { __half2 x; x.x = __float2half(v0); x.y = __float2half(v1); *(__half2*)(O + o) = x; }
        long long o2 = (tok0 + 8) * EMB + col0 + vt * 8;
        { __half2 x; x.x = __float2half(v2); x.y = __float2half(v3); *(__half2*)(O + o2) = x; }
    }
}

// ===================== LayerNorm -> fp16 ===============================
__global__ __launch_bounds__(256)
void layernorm_fp16_kernel(const float* __restrict__ x, const float* __restrict__ gamma,
                           const float* __restrict__ beta, fp16* __restrict__ o)
{
    long long row = blockIdx.x;
    const float4* xr = (const float4*)(x + row * EMB);
    float4 v = xr[threadIdx.x];
    float s  = v.x + v.y + v.z + v.w;
    float ss = v.x * v.x + v.y * v.y + v.z * v.z + v.w * v.w;
#pragma unroll
    for (int of = 16; of; of >>= 1) {
        s  += __shfl_xor_sync(0xffffffffu, s,  of);
        ss += __shfl_xor_sync(0xffffffffu, ss, of);
    }
    __shared__ float sh_s[8], sh_ss[8];
    int w = threadIdx.x >> 5, l = threadIdx.x & 31;
    if (l == 0) { sh_s[w] = s; sh_ss[w] = ss; }
    __syncthreads();
    s = 0.f; ss = 0.f;
#pragma unroll
    for (int i = 0; i < 8; i++) { s += sh_s[i]; ss += sh_ss[i]; }
    float mu   = s * (1.0f / EMB);
    float var  = ss * (1.0f / EMB) - mu * mu;
    float rstd = rsqrtf(var + 1e-6f);
    float4 gv = ((const float4*)gamma)[threadIdx.x];
    float4 bv = ((const float4*)beta)[threadIdx.x];
    float o0 = (v.x - mu) * rstd * gv.x + bv.x;
    float o1 = (v.y - mu) * rstd * gv.y + bv.y;
    float o2 = (v.z - mu) * rstd * gv.z + bv.z;
    float o3 = (v.w - mu) * rstd * gv.w + bv.w;
    long long base = row * EMB + threadIdx.x * 4;
    __half2 a; a.x = __float2half(o0); a.y = __float2half(o1);
    __half2 b; b.x = __float2half(o2); b.y = __float2half(o3);
    *(__half2*)(o + base)     = a;
    *(__half2*)(o + base + 2) = b;
}

// ============ transpose-convert: fp32 [R,C] -> [C,R] fp16 ==============
__global__ __launch_bounds__(256)
void wt_prep_kernel(const float* __restrict__ src, int R, int C,
                    fp16* __restrict__ dh)
{
    __shared__ float t[32][33];
    int c0 = blockIdx.x * 32, r0 = blockIdx.y * 32;
    int tx = threadIdx.x & 31, ty = threadIdx.x >> 5;
#pragma unroll
    for (int i = ty; i < 32; i += 8)
        t[i][tx] = src[(long long)(r0 + i) * C + c0 + tx];
    __syncthreads();
#pragma unroll
    for (int i = ty; i < 32; i += 8) {
        long long o = (long long)(c0 + i) * R + r0 + tx;
        dh[o] = __float2half(t[tx][i]);
    }
}

// ============ V^T prep: v fp32 (b,n,h*64+d) -> vt fp16 [BH,64,SEQ] =====
__global__ __launch_bounds__(256)
void vt_prep_kernel(const float* __restrict__ v, fp16* __restrict__ dh)
{
    __shared__ float t[32][33];
    int bh = blockIdx.z, b = bh / NHEAD, h = bh % NHEAD;
    int n0 = blockIdx.x * 32, d0 = blockIdx.y * 32;
    int tx = threadIdx.x & 31, ty = threadIdx.x >> 5;
#pragma unroll
    for (int i = ty; i < 32; i += 8)
        t[i][tx] = v[((long long)(b * SEQ + n0 + i)) * EMB + h * HDIM + d0 + tx];
    __syncthreads();
#pragma unroll
    for (int i = ty; i < 32; i += 8) {
        long long o = ((long long)bh * HDIM + d0 + i) * SEQ + n0 + tx;
        dh[o] = __float2half(t[tx][i]);
    }
}

// ===================== host side =======================================
template<int BN, int WM, int WN, int EPI>
static void launch_gemm(const fp16* A, const fp16* B,
                        const float* bias, const float* resid,
                        float* C, fp16* Ch,
                        fp16* Qo, fp16* Ko, float* Vo,
                        int M, int N, int K, int ldc,
                        long long sA, long long sB,
                        int batch, int hdiv, long long sCb, long long sCh,
                        float alpha)
{
    constexpr int SMEM_BYTES = 3 * (128 * 128 + BN * 128);
    cudaFuncSetAttribute(gemm_mma<BN, WM, WN, EPI>,
                         cudaFuncAttributeMaxDynamicSharedMemorySize, SMEM_BYTES);
    dim3 grid(N / BN, M / 128, batch);
    gemm_mma<BN, WM, WN, EPI><<<grid, 256, SMEM_BYTES>>>(
        A, B, bias, resid, C, Ch, Qo, Ko, Vo,
        M, N, K, ldc, sA, sB, hdiv, sCb, sCh, alpha);
}

extern "C" void kernel_launch(void* const* d_in, const int* in_sizes, int n_in,
                              void* d_out, int out_size)
{
    const float* x      = (const float*)d_in[0];
    const float* ln1_g  = (const float*)d_in[1];
    const float* ln1_b  = (const float*)d_in[2];
    const float* w_qkv  = (const float*)d_in[3];
    const float* b_qkv  = (const float*)d_in[4];
    const float* w_proj = (const float*)d_in[5];
    const float* b_proj = (const float*)d_in[6];
    const float* ln2_g  = (const float*)d_in[7];
    const float* ln2_b  = (const float*)d_in[8];
    const float* w_fc1  = (const float*)d_in[9];
    const float* b_fc1  = (const float*)d_in[10];
    const float* w_fc2  = (const float*)d_in[11];
    const float* b_fc2  = (const float*)d_in[12];
    float* out = (float*)d_out;

    fp16 *wqkvT, *wprojT, *wfc1T, *wfc2T;
    fp16 *ln1, *qf, *kf, *vt, *am, *ln2, *hb;
    float *vbuf, *x1;
    cudaGetSymbolAddress((void**)&wqkvT, g_wqkvT);
    cudaGetSymbolAddress((void**)&wprojT, g_wprojT);
    cudaGetSymbolAddress((void**)&wfc1T, g_wfc1T);
    cudaGetSymbolAddress((void**)&wfc2T, g_wfc2T);
    cudaGetSymbolAddress((void**)&ln1, g_ln1);
    cudaGetSymbolAddress((void**)&qf, g_q);
    cudaGetSymbolAddress((void**)&kf, g_k);
    cudaGetSymbolAddress((void**)&vbuf, g_v);
    cudaGetSymbolAddress((void**)&vt, g_vt);
    cudaGetSymbolAddress((void**)&am, g_am);
    cudaGetSymbolAddress((void**)&x1, g_x1);
    cudaGetSymbolAddress((void**)&ln2, g_ln2);
    cudaGetSymbolAddress((void**)&hb, g_h);

    // 0) weight transpose-converts  W[K,N] -> Wt[N,K] fp16
    wt_prep_kernel<<<dim3(3 * EMB / 32, EMB / 32), 256>>>(w_qkv, EMB, 3 * EMB, wqkvT);
    wt_prep_kernel<<<dim3(EMB / 32, EMB / 32), 256>>>(w_proj, EMB, EMB, wprojT);
    wt_prep_kernel<<<dim3(HIDDEN / 32, EMB / 32), 256>>>(w_fc1, EMB, HIDDEN, wfc1T);
    wt_prep_kernel<<<dim3(EMB / 32, HIDDEN / 32), 256>>>(w_fc2, HIDDEN, EMB, wfc2T);

    // 1) LN1 -> fp16
    layernorm_fp16_kernel<<<TOK, 256>>>(x, ln1_g, ln1_b, ln1);

    // 2) QKV GEMM with fused q/k/v extraction (128x256 tile)
    launch_gemm<256, 64, 64, EPI_QKV>(ln1, wqkvT, b_qkv, nullptr,
                                      nullptr, nullptr, qf, kf, vbuf,
                                      TOK, 3 * EMB, EMB, 3 * EMB, 0, 0, 1, 1, 0, 0, 1.0f);

    // 3) V transpose -> fp16
    vt_prep_kernel<<<dim3(SEQ / 32, HDIM / 32, BH), 256>>>(vbuf, vt);

    // 4) fused flash attention -> merged heads fp16 (2 CTAs/SM)
    {
        constexpr int FSMEM = 48 * 1024;
        cudaFuncSetAttribute(flash_kernel,
                             cudaFuncAttributeMaxDynamicSharedMemorySize, FSMEM);
        dim3 grid(SEQ / 128, BH);
        flash_kernel<<<grid, 256, FSMEM>>>(qf, kf, vt, am);
    }

    // 5) proj + residual: x1 = am @ w_proj + b + x
    launch_gemm<256, 64, 64, EPI_BIAS_RES>(am, wprojT, b_proj, x,
                                           x1, nullptr, nullptr, nullptr, nullptr,
                                           TOK, EMB, EMB, EMB, 0, 0, 1, 1, 0, 0, 1.0f);

    // 6) LN2 -> fp16
    layernorm_fp16_kernel<<<TOK, 256>>>(x1, ln2_g, ln2_b, ln2);

    // 7) FC1 + GELU -> h fp16
    launch_gemm<256, 64, 64, EPI_GELU_H>(ln2, wfc1T, b_fc1, nullptr,
                                         nullptr, hb, nullptr, nullptr, nullptr,
                                         TOK, HIDDEN, EMB, HIDDEN, 0, 0, 1, 1, 0, 0, 1.0f);

    // 8) FC2 + bias + residual -> out
    launch_gemm<256, 64, 64, EPI_BIAS_RES>(hb, wfc2T, b_fc2, x1,
                                           out, nullptr, nullptr, nullptr, nullptr,
                                           TOK, EMB, HIDDEN, EMB, 0, 0, 1, 1, 0, 0, 1.0f);
}